// round 7
// baseline (speedup 1.0000x reference)
#include <cuda_runtime.h>
#include <cuda_fp16.h>
#include <cstdint>

// Problem constants
#define BATCH 1024
#define DIM   512
#define NCLS  50000
#define NSUB  3
#define NROWS (NCLS * NSUB)   // 150000
#define S_SCALE 50.0f
#define COS_M 0.8775825618903728f   // cos(0.5)
#define SIN_M 0.4794255386042030f   // sin(0.5)

// GEMM tiling: C[M=150000, N=1024] = Wn * En^T
#define MT 192                 // 64 classes per CTA tile
#define NTB 128                // batch cols per CTA
#define KC 64                  // K chunk (halves); 128B rows
#define NCHUNK (DIM / KC)      // 8
#define MTILES 782             // ceil(150000/192)
#define STAGES 3
#define A_STG_BYTES (MT * 128)    // 24576
#define B_STG_BYTES (NTB * 128)   // 16384
#define STG_BYTES   (A_STG_BYTES + B_STG_BYTES)  // 40960
#define SMEM_DYN    (STAGES * STG_BYTES)         // 122880
#define EPAD 130

// Prep/GEMM segmentation for stream overlap
#define NSEG 16
#define MT_SEG 49              // mtiles per segment (15*49 + 47 = 782)
#define ROWS_SEG (MT_SEG * MT) // 9408 W rows per segment

// Scratch (device globals: allocation-free contract)
__device__ __half g_eh[BATCH * DIM];
__device__ __half g_wh[(size_t)NROWS * DIM];
__device__ int g_labels[BATCH];

// ---------------- PTX helpers (compute_103-safe: sm_80 feature set) ----------------
__device__ __forceinline__ uint32_t smem_u32(const void* p) {
    uint32_t a;
    asm("{ .reg .u64 t; cvta.to.shared.u64 t, %1; cvt.u32.u64 %0, t; }" : "=r"(a) : "l"(p));
    return a;
}

__device__ __forceinline__ void cp16(uint32_t s, const void* g) {
    asm volatile("cp.async.cg.shared.global [%0], [%1], 16;"
                 :: "r"(s), "l"((unsigned long long)__cvta_generic_to_global(g)));
}
#define CP_COMMIT() asm volatile("cp.async.commit_group;" ::: "memory")

__device__ __forceinline__ void ldsm4(uint32_t (&r)[4], uint32_t addr) {
    asm volatile("ldmatrix.sync.aligned.m8n8.x4.shared.b16 {%0,%1,%2,%3}, [%4];"
                 : "=r"(r[0]), "=r"(r[1]), "=r"(r[2]), "=r"(r[3]) : "r"(addr));
}

__device__ __forceinline__ void mma16816(float (&d)[4], const uint32_t (&a)[4],
                                         uint32_t b0, uint32_t b1) {
    asm volatile("mma.sync.aligned.m16n8k16.row.col.f32.f16.f16.f32 "
                 "{%0,%1,%2,%3}, {%4,%5,%6,%7}, {%8,%9}, {%0,%1,%2,%3};"
                 : "+f"(d[0]), "+f"(d[1]), "+f"(d[2]), "+f"(d[3])
                 : "r"(a[0]), "r"(a[1]), "r"(a[2]), "r"(a[3]), "r"(b0), "r"(b1));
}

// ---------------- Label dtype normalizer ----------------
__global__ void label_fix_kernel(const void* __restrict__ lab) {
    __shared__ int not64;
    int tid = threadIdx.x;
    if (tid == 0) not64 = 0;
    __syncthreads();
    if (tid < 512) {
        long long v = ((const long long*)lab)[tid];   // first 4KB: safe either way
        if (v < 0 || v >= NCLS) not64 = 1;            // idempotent store
    }
    __syncthreads();
    if (not64) g_labels[tid] = ((const int*)lab)[tid];
    else       g_labels[tid] = (int)((const long long*)lab)[tid];
}

// ---------------- Normalize rows -> fp16 (row-offset segmented) ----------------
__global__ void norm_half_kernel(const float* __restrict__ src, int row0, int cnt, int is_w) {
    int wrow = (blockIdx.x * blockDim.x + threadIdx.x) >> 5;
    int lane = threadIdx.x & 31;
    if (wrow >= cnt) return;
    int row = row0 + wrow;

    __half* dst = is_w ? g_wh : g_eh;

    const float4* rp = (const float4*)(src + (size_t)row * DIM);
    float4 v[4];
    float ss = 0.f;
#pragma unroll
    for (int i = 0; i < 4; i++) {
        v[i] = rp[i * 32 + lane];
        ss += v[i].x * v[i].x + v[i].y * v[i].y + v[i].z * v[i].z + v[i].w * v[i].w;
    }
#pragma unroll
    for (int o = 16; o; o >>= 1) ss += __shfl_xor_sync(0xffffffffu, ss, o);

    float inv = 1.0f / fmaxf(sqrtf(ss), 1e-12f);

    uint2* dp = (uint2*)dst + (size_t)row * 128;
#pragma unroll
    for (int i = 0; i < 4; i++) {
        __half2 p0 = __floats2half2_rn(v[i].x * inv, v[i].y * inv);
        __half2 p1 = __floats2half2_rn(v[i].z * inv, v[i].w * inv);
        uint2 pk;
        pk.x = *(uint32_t*)&p0;
        pk.y = *(uint32_t*)&p1;
        dp[i * 32 + lane] = pk;
    }
}

// ---------------- GEMM + max/arcface epilogue (HMMA mma.sync, fp32 acc) ----------------
// Swizzled smem layout: byte = r*128 + ((c ^ (r&7)) << 4),  c = 16B-column (0..7)

__device__ __forceinline__ void load_stage(uint32_t st, int mrow0, int n0, int k0, int tid) {
    // A (W): 192 rows x 64 halves = 1536 x 16B units, 6/thread @256
#pragma unroll
    for (int j = 0; j < 6; j++) {
        int u = tid + j * 256;
        int r = u >> 3, cu = u & 7;
        int gr = mrow0 + r; gr = gr < NROWS ? gr : NROWS - 1;
        const __half* gp = g_wh + (size_t)gr * DIM + k0 + cu * 8;
        cp16(st + r * 128 + ((cu ^ (r & 7)) << 4), gp);
    }
    // B (E): 128 rows x 64 halves = 1024 units, 4/thread @256
#pragma unroll
    for (int j = 0; j < 4; j++) {
        int u = tid + j * 256;
        int r = u >> 3, cu = u & 7;
        const __half* gp = g_eh + (size_t)(n0 + r) * DIM + k0 + cu * 8;
        cp16(st + A_STG_BYTES + r * 128 + ((cu ^ (r & 7)) << 4), gp);
    }
}

__global__ __launch_bounds__(256, 1)
void arcface_gemm_kernel(float* __restrict__ out, int mtile0) {
    extern __shared__ __align__(128) char smem_raw[];
    const uint32_t sbase = smem_u32(smem_raw);

    const int tid  = threadIdx.x;
    const int wid  = tid >> 5;
    const int lane = tid & 31;
    const int ntile = blockIdx.x;            // 0..7 (fastest: share W panel in L2)
    const int mtile = mtile0 + blockIdx.y;
    const int mrow0 = mtile * MT;
    const int n0    = ntile * NTB;

    // warp tile: 48(M) x 64(N); warp grid 4(M) x 2(N)
    const int wm0 = (wid & 3) * 48;
    const int wn0 = (wid >> 2) * 64;

    int ra[3], xa[3];
#pragma unroll
    for (int i = 0; i < 3; i++) {
        int m = wm0 + 16 * i + (lane & 15);
        ra[i] = m * 128;
        xa[i] = m & 7;
    }
    const int selA = lane >> 4;
    int rb[4], xb[4];
#pragma unroll
    for (int g = 0; g < 4; g++) {
        int n = wn0 + 16 * g + ((lane >> 4) << 3) + (lane & 7);
        rb[g] = n * 128;
        xb[g] = n & 7;
    }
    const int selB = (lane >> 3) & 1;

    float acc[3][8][4];
#pragma unroll
    for (int i = 0; i < 3; i++)
#pragma unroll
        for (int g = 0; g < 8; g++)
#pragma unroll
            for (int q = 0; q < 4; q++) acc[i][g][q] = 0.f;

    // prologue: issue chunks 0,1
    load_stage(sbase + 0 * STG_BYTES, mrow0, n0, 0 * KC, tid); CP_COMMIT();
    load_stage(sbase + 1 * STG_BYTES, mrow0, n0, 1 * KC, tid); CP_COMMIT();

    for (int s = 0; s < NCHUNK; s++) {
        if (s < NCHUNK - 2) asm volatile("cp.async.wait_group 1;" ::: "memory");
        else                asm volatile("cp.async.wait_group 0;" ::: "memory");
        __syncthreads();

        if (s + 2 < NCHUNK) {
            load_stage(sbase + ((s + 2) % STAGES) * STG_BYTES, mrow0, n0, (s + 2) * KC, tid);
            CP_COMMIT();
        }

        const uint32_t ab = sbase + (s % STAGES) * STG_BYTES;
        const uint32_t bb = ab + A_STG_BYTES;
#pragma unroll
        for (int kk = 0; kk < 4; kk++) {
            uint32_t a[3][4];
            const int ca = kk * 2 + selA;
#pragma unroll
            for (int i = 0; i < 3; i++)
                ldsm4(a[i], ab + ra[i] + ((ca ^ xa[i]) << 4));

            uint32_t b[8][2];
            const int cb = kk * 2 + selB;
#pragma unroll
            for (int g = 0; g < 4; g++) {
                uint32_t r4[4];
                ldsm4(r4, bb + rb[g] + ((cb ^ xb[g]) << 4));
                b[2 * g][0] = r4[0]; b[2 * g][1] = r4[1];
                b[2 * g + 1][0] = r4[2]; b[2 * g + 1][1] = r4[3];
            }
#pragma unroll
            for (int i = 0; i < 3; i++)
#pragma unroll
                for (int g = 0; g < 8; g++)
                    mma16816(acc[i][g], a[i], b[g][0], b[g][1]);
        }
        __syncthreads();
    }

    // -------- epilogue: accum -> SMEM [192][130], then max3 + arcface + store --------
    float* ep = (float*)smem_raw;
#pragma unroll
    for (int i = 0; i < 3; i++) {
        int row = wm0 + 16 * i + (lane >> 2);
#pragma unroll
        for (int g = 0; g < 8; g++) {
            int col = wn0 + 8 * g + 2 * (lane & 3);
            *(float2*)&ep[row * EPAD + col]       = make_float2(acc[i][g][0], acc[i][g][1]);
            *(float2*)&ep[(row + 8) * EPAD + col] = make_float2(acc[i][g][2], acc[i][g][3]);
        }
    }
    __syncthreads();

    const int cls  = tid & 63;           // local class; lanes consecutive -> coalesced
    const int bg   = tid >> 6;           // 0..3
    const int clsG = mtile * 64 + cls;
    if (clsG < NCLS) {
        const int r3 = 3 * cls;
#pragma unroll 4
        for (int i = 0; i < 32; i++) {
            int b = bg * 32 + i;
            float v0 = ep[r3 * EPAD + b];
            float v1 = ep[(r3 + 1) * EPAD + b];
            float v2 = ep[(r3 + 2) * EPAD + b];
            float m = fmaxf(v0, fmaxf(v1, v2));
            float v = m;
            if (g_labels[n0 + b] == clsG) {
                float mc = fminf(fmaxf(m, -1.0f + 1e-7f), 1.0f - 1e-7f);
                v = mc * COS_M - sqrtf(fmaxf(1.0f - mc * mc, 0.0f)) * SIN_M;
            }
            out[(size_t)(n0 + b) * NCLS + clsG] = S_SCALE * v;
        }
    }
}

// ---------------- Launch: segmented prep on forked stream, GEMM gated per segment ----------------
extern "C" void kernel_launch(void* const* d_in, const int* in_sizes, int n_in,
                              void* d_out, int out_size) {
    (void)in_sizes; (void)n_in; (void)out_size;
    const float* emb = (const float*)d_in[0];
    const void*  lab = d_in[1];
    const float* wt  = (const float*)d_in[2];
    float* out = (float*)d_out;

    static cudaStream_t s1 = nullptr;
    static cudaEvent_t ev0 = nullptr;
    static cudaEvent_t evS[NSEG];
    if (!s1) {
        cudaStreamCreateWithFlags(&s1, cudaStreamNonBlocking);
        cudaEventCreateWithFlags(&ev0, cudaEventDisableTiming);
        for (int i = 0; i < NSEG; i++)
            cudaEventCreateWithFlags(&evS[i], cudaEventDisableTiming);
        cudaFuncSetAttribute(arcface_gemm_kernel,
                             cudaFuncAttributeMaxDynamicSharedMemorySize, SMEM_DYN);
    }

    // Fork: s1 branches off the (captured) default stream at the start.
    cudaEventRecord(ev0, 0);
    cudaStreamWaitEvent(s1, ev0, 0);

    // W prep segments 1..NSEG-1 on s1, each tagged with an event.
    for (int i = 1; i < NSEG; i++) {
        int row0 = i * ROWS_SEG;
        int cnt  = (row0 + ROWS_SEG <= NROWS) ? ROWS_SEG : (NROWS - row0);
        int blocks = (cnt + 7) / 8;
        norm_half_kernel<<<blocks, 256, 0, s1>>>(wt, row0, cnt, 1);
        cudaEventRecord(evS[i], s1);
    }

    // Default stream: labels, E, W segment 0.
    label_fix_kernel<<<1, 1024>>>(lab);
    norm_half_kernel<<<BATCH / 8, 256>>>(emb, 0, BATCH, 0);
    norm_half_kernel<<<ROWS_SEG / 8, 256>>>(wt, 0, ROWS_SEG, 1);

    // GEMM segments: seg 0 ready in-stream; seg i waits on its prep event (joins s1).
    for (int i = 0; i < NSEG; i++) {
        if (i > 0) cudaStreamWaitEvent(0, evS[i], 0);
        int m0 = i * MT_SEG;
        int mcnt = (i == NSEG - 1) ? (MTILES - m0) : MT_SEG;
        dim3 grid(BATCH / NTB, mcnt);
        arcface_gemm_kernel<<<grid, 256, SMEM_DYN>>>(out, m0);
    }
}

// round 8
// speedup vs baseline: 1.0583x; 1.0583x over previous
#include <cuda_runtime.h>
#include <cuda_fp16.h>
#include <cstdint>

// Problem constants
#define BATCH 1024
#define DIM   512
#define NCLS  50000
#define NSUB  3
#define NROWS (NCLS * NSUB)   // 150000
#define S_SCALE 50.0f
#define COS_M 0.8775825618903728f   // cos(0.5)
#define SIN_M 0.4794255386042030f   // sin(0.5)

// GEMM tiling: C[M=150000, N=1024] = W * En^T (W raw fp32, normalized in epilogue)
#define MT 192                 // 64 classes per CTA tile
#define NTB 128                // batch cols per CTA
#define KC 64                  // K chunk (halves); 128B rows
#define NCHUNK (DIM / KC)      // 8
#define MTILES 782             // ceil(150000/192)
#define W_SCALE 256.0f         // exact pow2: lifts tiny weights out of fp16 subnormals

// SMEM layout (bytes from base)
#define OFF_A   0                    // 2 x 24576 fp16 A buffers
#define A_BUF_BYTES 24576
#define OFF_B   49152                // 3 x 16384 fp16 B buffers
#define B_BUF_BYTES 16384
#define EPAD 130                     // epilogue: [192][130] floats = 99840 B (overwrites A/B)
#define OFF_SQ  99840                // 192 x 16 partial sumsq = 12288 B
#define OFF_INV 112128               // 192 inv norms = 768 B
#define SMEM_DYN 112896

// Scratch (device globals: allocation-free contract)
__device__ __half g_eh[BATCH * DIM];
__device__ int g_labels[BATCH];

// ---------------- PTX helpers (compute_103-safe: sm_80 feature set) ----------------
__device__ __forceinline__ uint32_t smem_u32(const void* p) {
    uint32_t a;
    asm("{ .reg .u64 t; cvta.to.shared.u64 t, %1; cvt.u32.u64 %0, t; }" : "=r"(a) : "l"(p));
    return a;
}

__device__ __forceinline__ void cp16(uint32_t s, const void* g) {
    asm volatile("cp.async.cg.shared.global [%0], [%1], 16;"
                 :: "r"(s), "l"((unsigned long long)__cvta_generic_to_global(g)));
}
#define CP_COMMIT() asm volatile("cp.async.commit_group;" ::: "memory")

__device__ __forceinline__ void ldsm4(uint32_t (&r)[4], uint32_t addr) {
    asm volatile("ldmatrix.sync.aligned.m8n8.x4.shared.b16 {%0,%1,%2,%3}, [%4];"
                 : "=r"(r[0]), "=r"(r[1]), "=r"(r[2]), "=r"(r[3]) : "r"(addr));
}

__device__ __forceinline__ void mma16816(float (&d)[4], const uint32_t (&a)[4],
                                         uint32_t b0, uint32_t b1) {
    asm volatile("mma.sync.aligned.m16n8k16.row.col.f32.f16.f16.f32 "
                 "{%0,%1,%2,%3}, {%4,%5,%6,%7}, {%8,%9}, {%0,%1,%2,%3};"
                 : "+f"(d[0]), "+f"(d[1]), "+f"(d[2]), "+f"(d[3])
                 : "r"(a[0]), "r"(a[1]), "r"(a[2]), "r"(a[3]), "r"(b0), "r"(b1));
}

__device__ __forceinline__ void sts64(uint32_t addr, uint32_t x, uint32_t y) {
    asm volatile("st.shared.v2.b32 [%0], {%1,%2};" :: "r"(addr), "r"(x), "r"(y));
}

// ---------------- Label dtype normalizer ----------------
__global__ void label_fix_kernel(const void* __restrict__ lab) {
    __shared__ int not64;
    int tid = threadIdx.x;
    if (tid == 0) not64 = 0;
    __syncthreads();
    if (tid < 512) {
        long long v = ((const long long*)lab)[tid];   // first 4KB: safe either way
        if (v < 0 || v >= NCLS) not64 = 1;            // idempotent store
    }
    __syncthreads();
    if (not64) g_labels[tid] = ((const int*)lab)[tid];
    else       g_labels[tid] = (int)((const long long*)lab)[tid];
}

// ---------------- Normalize E rows -> fp16 ----------------
__global__ void norm_half_kernel(const float* __restrict__ src) {
    int row  = (blockIdx.x * blockDim.x + threadIdx.x) >> 5;
    int lane = threadIdx.x & 31;
    if (row >= BATCH) return;

    const float4* rp = (const float4*)(src + (size_t)row * DIM);
    float4 v[4];
    float ss = 0.f;
#pragma unroll
    for (int i = 0; i < 4; i++) {
        v[i] = rp[i * 32 + lane];
        ss += v[i].x * v[i].x + v[i].y * v[i].y + v[i].z * v[i].z + v[i].w * v[i].w;
    }
#pragma unroll
    for (int o = 16; o; o >>= 1) ss += __shfl_xor_sync(0xffffffffu, ss, o);

    float inv = 1.0f / fmaxf(sqrtf(ss), 1e-12f);

    uint2* dp = (uint2*)g_eh + (size_t)row * 128;
#pragma unroll
    for (int i = 0; i < 4; i++) {
        __half2 p0 = __floats2half2_rn(v[i].x * inv, v[i].y * inv);
        __half2 p1 = __floats2half2_rn(v[i].z * inv, v[i].w * inv);
        uint2 pk;
        pk.x = *(uint32_t*)&p0;
        pk.y = *(uint32_t*)&p1;
        dp[i * 32 + lane] = pk;
    }
}

// ---------------- Fused GEMM: raw fp32 W -> fp16 in-register + sumsq + arcface ----------------
// fp16 smem tile swizzle: byte = r*128 + ((c16 ^ (r&7)) << 4)

__device__ __forceinline__ void load_B(uint32_t st, int n0, int k0, int tid) {
    // B (E): 128 rows x 64 halves = 1024 x 16B units, 4/thread @256
#pragma unroll
    for (int j = 0; j < 4; j++) {
        int u = tid + j * 256;
        int r = u >> 3, cu = u & 7;
        const __half* gp = g_eh + (size_t)(n0 + r) * DIM + k0 + cu * 8;
        cp16(st + r * 128 + ((cu ^ (r & 7)) << 4), gp);
    }
}

// A fp32: 192 rows x 64 floats per stage = 3072 float4; 12/thread.
// thread -> (row, c) fixed: u = tid + j*256, r = u>>4, c = u&15 (float4 within row)
__device__ __forceinline__ void load_A_regs(float4 (&stg)[12], const float* __restrict__ wt,
                                            int mrow0, int k0, int tid) {
#pragma unroll
    for (int j = 0; j < 12; j++) {
        int u = tid + j * 256;
        int r = u >> 4, c = u & 15;
        int gr = mrow0 + r; gr = gr < NROWS ? gr : NROWS - 1;
        stg[j] = __ldg((const float4*)(wt + (size_t)gr * DIM + k0) + c);
    }
}

__device__ __forceinline__ void cvt_sts_A(const float4 (&stg)[12], uint32_t abuf,
                                          float (&ss)[12], int tid) {
#pragma unroll
    for (int j = 0; j < 12; j++) {
        int u = tid + j * 256;
        int r = u >> 4, c = u & 15;
        float4 f = stg[j];
        ss[j] += f.x * f.x + f.y * f.y + f.z * f.z + f.w * f.w;
        __half2 h0 = __floats2half2_rn(f.x * W_SCALE, f.y * W_SCALE);
        __half2 h1 = __floats2half2_rn(f.z * W_SCALE, f.w * W_SCALE);
        uint32_t addr = abuf + r * 128 + (((c >> 1) ^ (r & 7)) << 4) + (c & 1) * 8;
        sts64(addr, *(uint32_t*)&h0, *(uint32_t*)&h1);
    }
}

__global__ __launch_bounds__(256, 1)
void arcface_gemm_kernel(const float* __restrict__ wt, float* __restrict__ out) {
    extern __shared__ __align__(128) char smem_raw[];
    const uint32_t sbase = smem_u32(smem_raw);

    const int tid  = threadIdx.x;
    const int wid  = tid >> 5;
    const int lane = tid & 31;
    const int ntile = blockIdx.x;        // 0..7 (fastest: 8 CTAs share W rows via L2)
    const int mtile = blockIdx.y;        // 0..781
    const int mrow0 = mtile * MT;
    const int n0    = ntile * NTB;

    // warp tile: 48(M) x 64(N); warp grid 4(M) x 2(N)
    const int wm0 = (wid & 3) * 48;
    const int wn0 = (wid >> 2) * 64;

    int ra[3], xa[3];
#pragma unroll
    for (int i = 0; i < 3; i++) {
        int m = wm0 + 16 * i + (lane & 15);
        ra[i] = m * 128;
        xa[i] = m & 7;
    }
    const int selA = lane >> 4;
    int rb[4], xb[4];
#pragma unroll
    for (int g = 0; g < 4; g++) {
        int n = wn0 + 16 * g + ((lane >> 4) << 3) + (lane & 7);
        rb[g] = n * 128;
        xb[g] = n & 7;
    }
    const int selB = (lane >> 3) & 1;

    float acc[3][8][4];
#pragma unroll
    for (int i = 0; i < 3; i++)
#pragma unroll
        for (int g = 0; g < 8; g++)
#pragma unroll
            for (int q = 0; q < 4; q++) acc[i][g][q] = 0.f;

    float ss[12];
#pragma unroll
    for (int j = 0; j < 12; j++) ss[j] = 0.f;

    // prologue: B stages 0,1 via cp.async; A stage 0 via LDG+cvt+STS
    load_B(sbase + OFF_B + 0 * B_BUF_BYTES, n0, 0 * KC, tid); CP_COMMIT();
    load_B(sbase + OFF_B + 1 * B_BUF_BYTES, n0, 1 * KC, tid); CP_COMMIT();
    float4 stg[12];
    load_A_regs(stg, wt, mrow0, 0, tid);
    cvt_sts_A(stg, sbase + OFF_A + 0 * A_BUF_BYTES, ss, tid);

    for (int s = 0; s < NCHUNK; s++) {
        if (s < NCHUNK - 1) asm volatile("cp.async.wait_group 1;" ::: "memory");
        else                asm volatile("cp.async.wait_group 0;" ::: "memory");
        __syncthreads();

        // prefetch next A chunk into regs (consumed after the kk-loop)
        if (s + 1 < NCHUNK) load_A_regs(stg, wt, mrow0, (s + 1) * KC, tid);
        if (s + 2 < NCHUNK) {
            load_B(sbase + OFF_B + ((s + 2) % 3) * B_BUF_BYTES, n0, (s + 2) * KC, tid);
            CP_COMMIT();
        }

        const uint32_t ab = sbase + OFF_A + (s & 1) * A_BUF_BYTES;
        const uint32_t bb = sbase + OFF_B + (s % 3) * B_BUF_BYTES;
#pragma unroll
        for (int kk = 0; kk < 4; kk++) {
            uint32_t a[3][4];
            const int ca = kk * 2 + selA;
#pragma unroll
            for (int i = 0; i < 3; i++)
                ldsm4(a[i], ab + ra[i] + ((ca ^ xa[i]) << 4));

            uint32_t b[8][2];
            const int cb = kk * 2 + selB;
#pragma unroll
            for (int g = 0; g < 4; g++) {
                uint32_t r4[4];
                ldsm4(r4, bb + rb[g] + ((cb ^ xb[g]) << 4));
                b[2 * g][0] = r4[0]; b[2 * g][1] = r4[1];
                b[2 * g + 1][0] = r4[2]; b[2 * g + 1][1] = r4[3];
            }
#pragma unroll
            for (int i = 0; i < 3; i++)
#pragma unroll
                for (int g = 0; g < 8; g++)
                    mma16816(acc[i][g], a[i], b[g][0], b[g][1]);
        }

        if (s + 1 < NCHUNK)
            cvt_sts_A(stg, sbase + OFF_A + ((s + 1) & 1) * A_BUF_BYTES, ss, tid);
        __syncthreads();
    }

    // -------- W-row inverse norms from on-the-fly sumsq --------
    float* sq  = (float*)(smem_raw + OFF_SQ);    // [192][16]
    float* inv = (float*)(smem_raw + OFF_INV);   // [192]
#pragma unroll
    for (int j = 0; j < 12; j++) {
        int u = tid + j * 256;
        sq[(u >> 4) * 16 + (tid & 15)] = ss[j];
    }
    __syncthreads();
    if (tid < 192) {
        float t = 0.f;
#pragma unroll
        for (int c = 0; c < 16; c++) t += sq[tid * 16 + c];
        // cosine = dot(W*256, e_n) / max(|W*256|, 256*eps)
        inv[tid] = 1.0f / fmaxf(sqrtf(t) * W_SCALE, W_SCALE * 1e-12f);
    }
    __syncthreads();

    // -------- epilogue: accum -> SMEM [192][130], then norm + max3 + arcface --------
    float* ep = (float*)smem_raw;
#pragma unroll
    for (int i = 0; i < 3; i++) {
        int row = wm0 + 16 * i + (lane >> 2);
#pragma unroll
        for (int g = 0; g < 8; g++) {
            int col = wn0 + 8 * g + 2 * (lane & 3);
            *(float2*)&ep[row * EPAD + col]       = make_float2(acc[i][g][0], acc[i][g][1]);
            *(float2*)&ep[(row + 8) * EPAD + col] = make_float2(acc[i][g][2], acc[i][g][3]);
        }
    }
    __syncthreads();

    const int cls  = tid & 63;           // local class; lanes consecutive -> coalesced
    const int bg   = tid >> 6;           // 0..3
    const int clsG = mtile * 64 + cls;
    if (clsG < NCLS) {
        const int r3 = 3 * cls;
        const float i0 = inv[r3], i1 = inv[r3 + 1], i2 = inv[r3 + 2];
#pragma unroll 4
        for (int i = 0; i < 32; i++) {
            int b = bg * 32 + i;
            float v0 = ep[r3 * EPAD + b] * i0;
            float v1 = ep[(r3 + 1) * EPAD + b] * i1;
            float v2 = ep[(r3 + 2) * EPAD + b] * i2;
            float m = fmaxf(v0, fmaxf(v1, v2));
            float v = m;
            if (g_labels[n0 + b] == clsG) {
                float mc = fminf(fmaxf(m, -1.0f + 1e-7f), 1.0f - 1e-7f);
                v = mc * COS_M - sqrtf(fmaxf(1.0f - mc * mc, 0.0f)) * SIN_M;
            }
            out[(size_t)(n0 + b) * NCLS + clsG] = S_SCALE * v;
        }
    }
}

// ---------------- Launch ----------------
extern "C" void kernel_launch(void* const* d_in, const int* in_sizes, int n_in,
                              void* d_out, int out_size) {
    (void)in_sizes; (void)n_in; (void)out_size;
    const float* emb = (const float*)d_in[0];
    const void*  lab = d_in[1];
    const float* wt  = (const float*)d_in[2];
    float* out = (float*)d_out;

    cudaFuncSetAttribute(arcface_gemm_kernel,
                         cudaFuncAttributeMaxDynamicSharedMemorySize, SMEM_DYN);

    label_fix_kernel<<<1, 1024>>>(lab);
    norm_half_kernel<<<BATCH / 8, 256>>>(emb);   // E only (1 MB); W consumed raw by GEMM

    dim3 grid(BATCH / NTB, MTILES);   // (8, 782), ntile fastest
    arcface_gemm_kernel<<<grid, 256, SMEM_DYN>>>(wt, out);
}

// round 10
// speedup vs baseline: 1.1126x; 1.0513x over previous
#include <cuda_runtime.h>
#include <cuda_fp16.h>
#include <cstdint>

// Problem constants
#define BATCH 1024
#define DIM   512
#define NCLS  50000
#define NSUB  3
#define NROWS (NCLS * NSUB)   // 150000
#define S_SCALE 50.0f
#define COS_M 0.8775825618903728f   // cos(0.5)
#define SIN_M 0.4794255386042030f   // sin(0.5)

// GEMM tiling: C[M=150000, N=1024] = Wn * En^T
#define MT 192                 // 64 classes per CTA tile
#define NTB 128                // batch cols per CTA
#define KC 64                  // K chunk (halves); 128B rows
#define NCHUNK (DIM / KC)      // 8
#define MTILES 782             // ceil(150000/192)
#define STAGES 3
#define A_STG_BYTES (MT * 128)    // 24576
#define B_STG_BYTES (NTB * 128)   // 16384
#define STG_BYTES   (A_STG_BYTES + B_STG_BYTES)  // 40960
#define SMEM_DYN    (STAGES * STG_BYTES)         // 122880
#define EPAD 130

// W-prep progress segmentation: seg = 50 mtiles = 9600 rows = 1200 prep blocks
#define NSEGF 16
#define PREP_BLOCKS 18750          // 8 rows per block
#define BLOCKS_PER_SEG 1200        // last seg: 750
#define SPIN_LIMIT 50000           // x ~64ns -> ~3ms bound, then self-prep fallback

// Scratch (device globals: allocation-free contract)
__device__ __half g_eh[BATCH * DIM];
__device__ __half g_wh[(size_t)NROWS * DIM];
__device__ int g_labels[BATCH];
__device__ int g_cnt[NSEGF];

// ---------------- PTX helpers (compute_103-safe: sm_80 feature set) ----------------
__device__ __forceinline__ uint32_t smem_u32(const void* p) {
    uint32_t a;
    asm("{ .reg .u64 t; cvta.to.shared.u64 t, %1; cvt.u32.u64 %0, t; }" : "=r"(a) : "l"(p));
    return a;
}

__device__ __forceinline__ void cp16(uint32_t s, const void* g) {
    asm volatile("cp.async.cg.shared.global [%0], [%1], 16;"
                 :: "r"(s), "l"((unsigned long long)__cvta_generic_to_global(g)));
}
#define CP_COMMIT() asm volatile("cp.async.commit_group;" ::: "memory")

__device__ __forceinline__ void ldsm4(uint32_t (&r)[4], uint32_t addr) {
    asm volatile("ldmatrix.sync.aligned.m8n8.x4.shared.b16 {%0,%1,%2,%3}, [%4];"
                 : "=r"(r[0]), "=r"(r[1]), "=r"(r[2]), "=r"(r[3]) : "r"(addr));
}

__device__ __forceinline__ void mma16816(float (&d)[4], const uint32_t (&a)[4],
                                         uint32_t b0, uint32_t b1) {
    asm volatile("mma.sync.aligned.m16n8k16.row.col.f32.f16.f16.f32 "
                 "{%0,%1,%2,%3}, {%4,%5,%6,%7}, {%8,%9}, {%0,%1,%2,%3};"
                 : "+f"(d[0]), "+f"(d[1]), "+f"(d[2]), "+f"(d[3])
                 : "r"(a[0]), "r"(a[1]), "r"(a[2]), "r"(a[3]), "r"(b0), "r"(b1));
}

// Normalize one row (warp-collective) from fp32 src into fp16 dst.
__device__ __forceinline__ void norm_row_warp(const float* __restrict__ src,
                                              __half* __restrict__ dst,
                                              int row, int lane) {
    const float4* rp = (const float4*)(src + (size_t)row * DIM);
    float4 v[4];
    float ss = 0.f;
#pragma unroll
    for (int i = 0; i < 4; i++) {
        v[i] = rp[i * 32 + lane];
        ss += v[i].x * v[i].x + v[i].y * v[i].y + v[i].z * v[i].z + v[i].w * v[i].w;
    }
#pragma unroll
    for (int o = 16; o; o >>= 1) ss += __shfl_xor_sync(0xffffffffu, ss, o);

    float inv = 1.0f / fmaxf(sqrtf(ss), 1e-12f);

    uint2* dp = (uint2*)dst + (size_t)row * 128;
#pragma unroll
    for (int i = 0; i < 4; i++) {
        __half2 p0 = __floats2half2_rn(v[i].x * inv, v[i].y * inv);
        __half2 p1 = __floats2half2_rn(v[i].z * inv, v[i].w * inv);
        uint2 pk;
        pk.x = *(uint32_t*)&p0;
        pk.y = *(uint32_t*)&p1;
        dp[i * 32 + lane] = pk;
    }
}

// ---------------- E normalize + labels + counter reset (origin stream, first) ----------------
__global__ void norm_e_label_kernel(const float* __restrict__ src, const void* __restrict__ lab) {
    const int tid = threadIdx.x;

    if (blockIdx.x == 0) {
        __shared__ int not64;
        if (tid == 0) not64 = 0;
        if (tid < NSEGF) g_cnt[tid] = 0;            // reset per-replay progress counters
        __syncthreads();
        if (tid < 256) {
#pragma unroll
            for (int j = 0; j < 2; j++) {
                long long v = ((const long long*)lab)[tid * 2 + j];  // first 4KB: safe either way
                if (v < 0 || v >= NCLS) not64 = 1;                   // idempotent store
            }
        }
        __syncthreads();
#pragma unroll
        for (int j = 0; j < 4; j++) {
            int i = tid + j * 256;
            if (not64) g_labels[i] = ((const int*)lab)[i];
            else       g_labels[i] = (int)((const long long*)lab)[i];
        }
    }

    int row  = blockIdx.x * 8 + (tid >> 5);   // 128 blocks x 8 warps = 1024 rows
    norm_row_warp(src, g_eh, row, tid & 31);
}

// ---------------- W normalize -> fp16 with per-segment completion counters ----------------
__global__ void norm_w_kernel(const float* __restrict__ src) {
    const int tid = threadIdx.x;
    int row = blockIdx.x * 8 + (tid >> 5);
    if (row < NROWS) norm_row_warp(src, g_wh, row, tid & 31);
    __syncthreads();
    __threadfence();                       // release: rows visible before count bump
    if (tid == 0) atomicAdd(&g_cnt[blockIdx.x / BLOCKS_PER_SEG], 1);
}

// ---------------- GEMM + max/arcface epilogue (HMMA mma.sync, fp32 acc) ----------------
// Swizzled smem layout: byte = r*128 + ((c ^ (r&7)) << 4),  c = 16B-column (0..7)

__device__ __forceinline__ void load_stage(uint32_t st, int mrow0, int n0, int k0, int tid) {
    // A (W): 192 rows x 64 halves = 1536 x 16B units, 6/thread @256
#pragma unroll
    for (int j = 0; j < 6; j++) {
        int u = tid + j * 256;
        int r = u >> 3, cu = u & 7;
        int gr = mrow0 + r; gr = gr < NROWS ? gr : NROWS - 1;
        const __half* gp = g_wh + (size_t)gr * DIM + k0 + cu * 8;
        cp16(st + r * 128 + ((cu ^ (r & 7)) << 4), gp);
    }
    // B (E): 128 rows x 64 halves = 1024 units, 4/thread @256
#pragma unroll
    for (int j = 0; j < 4; j++) {
        int u = tid + j * 256;
        int r = u >> 3, cu = u & 7;
        const __half* gp = g_eh + (size_t)(n0 + r) * DIM + k0 + cu * 8;
        cp16(st + A_STG_BYTES + r * 128 + ((cu ^ (r & 7)) << 4), gp);
    }
}

__global__ __launch_bounds__(256, 1)
void arcface_gemm_kernel(const float* __restrict__ wt_raw, float* __restrict__ out) {
    extern __shared__ __align__(128) char smem_raw[];
    const uint32_t sbase = smem_u32(smem_raw);

    const int tid  = threadIdx.x;
    const int wid  = tid >> 5;
    const int lane = tid & 31;
    const int ntile = blockIdx.x;        // 0..7 (fastest: share W panel in L2)
    const int mtile = blockIdx.y;        // 0..781
    const int mrow0 = mtile * MT;
    const int n0    = ntile * NTB;

    // Bounded wait for this mtile's W segment; on timeout, self-prep (hang-proof).
    __shared__ int s_ready;
    if (tid == 0) {
        const int seg = mtile / 50;
        const int needed = (seg == NSEGF - 1) ? (PREP_BLOCKS - (NSEGF - 1) * BLOCKS_PER_SEG)
                                              : BLOCKS_PER_SEG;
        volatile int* cp = (volatile int*)&g_cnt[seg];
        int it = 0, ok = 0;
        while (it++ < SPIN_LIMIT) {
            if (*cp >= needed) { ok = 1; break; }
            __nanosleep(64);
        }
        __threadfence();                 // acquire
        s_ready = ok;
    }
    __syncthreads();
    if (!s_ready) {
        // Fallback: normalize this CTA's own 192 rows (identical math; benign dup writes).
#pragma unroll 1
        for (int i = 0; i < 24; i++) {
            int row = mrow0 + wid + i * 8;
            if (row < NROWS) norm_row_warp(wt_raw, g_wh, row, lane);
        }
        __threadfence();
        __syncthreads();
    }

    // warp tile: 48(M) x 64(N); warp grid 4(M) x 2(N)
    const int wm0 = (wid & 3) * 48;
    const int wn0 = (wid >> 2) * 64;

    int ra[3], xa[3];
#pragma unroll
    for (int i = 0; i < 3; i++) {
        int m = wm0 + 16 * i + (lane & 15);
        ra[i] = m * 128;
        xa[i] = m & 7;
    }
    const int selA = lane >> 4;
    int rb[4], xb[4];
#pragma unroll
    for (int g = 0; g < 4; g++) {
        int n = wn0 + 16 * g + ((lane >> 4) << 3) + (lane & 7);
        rb[g] = n * 128;
        xb[g] = n & 7;
    }
    const int selB = (lane >> 3) & 1;

    float acc[3][8][4];
#pragma unroll
    for (int i = 0; i < 3; i++)
#pragma unroll
        for (int g = 0; g < 8; g++)
#pragma unroll
            for (int q = 0; q < 4; q++) acc[i][g][q] = 0.f;

    // prologue: issue chunks 0,1
    load_stage(sbase + 0 * STG_BYTES, mrow0, n0, 0 * KC, tid); CP_COMMIT();
    load_stage(sbase + 1 * STG_BYTES, mrow0, n0, 1 * KC, tid); CP_COMMIT();

    for (int s = 0; s < NCHUNK; s++) {
        if (s < NCHUNK - 2) asm volatile("cp.async.wait_group 1;" ::: "memory");
        else                asm volatile("cp.async.wait_group 0;" ::: "memory");
        __syncthreads();

        if (s + 2 < NCHUNK) {
            load_stage(sbase + ((s + 2) % STAGES) * STG_BYTES, mrow0, n0, (s + 2) * KC, tid);
            CP_COMMIT();
        }

        const uint32_t ab = sbase + (s % STAGES) * STG_BYTES;
        const uint32_t bb = ab + A_STG_BYTES;
#pragma unroll
        for (int kk = 0; kk < 4; kk++) {
            uint32_t a[3][4];
            const int ca = kk * 2 + selA;
#pragma unroll
            for (int i = 0; i < 3; i++)
                ldsm4(a[i], ab + ra[i] + ((ca ^ xa[i]) << 4));

            uint32_t b[8][2];
            const int cb = kk * 2 + selB;
#pragma unroll
            for (int g = 0; g < 4; g++) {
                uint32_t r4[4];
                ldsm4(r4, bb + rb[g] + ((cb ^ xb[g]) << 4));
                b[2 * g][0] = r4[0]; b[2 * g][1] = r4[1];
                b[2 * g + 1][0] = r4[2]; b[2 * g + 1][1] = r4[3];
            }
#pragma unroll
            for (int i = 0; i < 3; i++)
#pragma unroll
                for (int g = 0; g < 8; g++)
                    mma16816(acc[i][g], a[i], b[g][0], b[g][1]);
        }
        __syncthreads();
    }

    // -------- epilogue: accum -> SMEM [192][130], then max3 + arcface + store --------
    float* ep = (float*)smem_raw;
#pragma unroll
    for (int i = 0; i < 3; i++) {
        int row = wm0 + 16 * i + (lane >> 2);
#pragma unroll
        for (int g = 0; g < 8; g++) {
            int col = wn0 + 8 * g + 2 * (lane & 3);
            *(float2*)&ep[row * EPAD + col]       = make_float2(acc[i][g][0], acc[i][g][1]);
            *(float2*)&ep[(row + 8) * EPAD + col] = make_float2(acc[i][g][2], acc[i][g][3]);
        }
    }
    __syncthreads();

    const int cls  = tid & 63;           // local class; lanes consecutive -> coalesced
    const int bg   = tid >> 6;           // 0..3
    const int clsG = mtile * 64 + cls;
    if (clsG < NCLS) {
        const int r3 = 3 * cls;
#pragma unroll 4
        for (int i = 0; i < 32; i++) {
            int b = bg * 32 + i;
            float v0 = ep[r3 * EPAD + b];
            float v1 = ep[(r3 + 1) * EPAD + b];
            float v2 = ep[(r3 + 2) * EPAD + b];
            float m = fmaxf(v0, fmaxf(v1, v2));
            float v = m;
            if (g_labels[n0 + b] == clsG) {
                float mc = fminf(fmaxf(m, -1.0f + 1e-7f), 1.0f - 1e-7f);
                v = mc * COS_M - sqrtf(fmaxf(1.0f - mc * mc, 0.0f)) * SIN_M;
            }
            out[(size_t)(n0 + b) * NCLS + clsG] = S_SCALE * v;
        }
    }
}

// ---------------- Launch: prep on origin, GEMM concurrent on forked stream ----------------
extern "C" void kernel_launch(void* const* d_in, const int* in_sizes, int n_in,
                              void* d_out, int out_size) {
    (void)in_sizes; (void)n_in; (void)out_size;
    const float* emb = (const float*)d_in[0];
    const void*  lab = d_in[1];
    const float* wt  = (const float*)d_in[2];
    float* out = (float*)d_out;

    static cudaStream_t s1 = nullptr;
    static cudaEvent_t ev0 = nullptr, ev1 = nullptr;
    if (!s1) {
        cudaStreamCreateWithFlags(&s1, cudaStreamNonBlocking);
        cudaEventCreateWithFlags(&ev0, cudaEventDisableTiming);
        cudaEventCreateWithFlags(&ev1, cudaEventDisableTiming);
        cudaFuncSetAttribute(arcface_gemm_kernel,
                             cudaFuncAttributeMaxDynamicSharedMemorySize, SMEM_DYN);
    }

    // Origin: counters + labels + E-norm (GEMM prerequisites except W).
    norm_e_label_kernel<<<BATCH / 8, 256>>>(emb, lab);

    // Fork s1 after prerequisites.
    cudaEventRecord(ev0, 0);
    cudaStreamWaitEvent(s1, ev0, 0);

    // Origin: W prep (publishes per-segment progress).
    norm_w_kernel<<<PREP_BLOCKS, 256>>>(wt);

    // s1: monolithic GEMM; each CTA bounded-waits on its W segment (self-prep fallback).
    dim3 grid(BATCH / NTB, MTILES);   // (8, 782), ntile fastest
    arcface_gemm_kernel<<<grid, 256, SMEM_DYN, s1>>>(wt, out);

    // Join back to origin so the graph's leaf includes the GEMM.
    cudaEventRecord(ev1, s1);
    cudaStreamWaitEvent(0, ev1, 0);
}